// round 2
// baseline (speedup 1.0000x reference)
#include <cuda_runtime.h>
#include <cstdint>

#define KE 16
#define KD 1024
#define KF 4096
#define KT 4096
#define KA 8192
#define KSEG 4194304  /* KF*KD elements per expert matrix */

// ---------------- device scratch (static; no allocations) ----------------
__device__ int8_t g_w1q[(size_t)KE*KSEG];   // 64 MB ternary int8
__device__ int8_t g_w2q[(size_t)KE*KSEG];   // 64 MB
__device__ int8_t g_qa[(size_t)KA*KD];      // 8 MB quantized activations (gemm1 A)
__device__ int8_t g_qh[(size_t)KA*KF];      // 32 MB quantized hidden (gemm2 A)
__device__ float  g_h[(size_t)KA*KF];       // 128 MB fp32 hidden (gelu output)
__device__ float  g_part[(size_t)KA*KD];    // 32 MB per-assignment output rows
__device__ float  g_wsum[32];               // sum |w| per (matrix, expert)
__device__ float  g_ra[KA];                 // 1/act_scale for gemm1 rows
__device__ float  g_rh[KA];                 // 1/act_scale for gemm2 rows
__device__ float  g_ir[KT];                 // per-token inv rms of x
__device__ int    g_te[KT*2];               // top-2 expert ids per token
__device__ float  g_tw[KT*2];               // top-2 combine weights
__device__ float  g_ps[KE];                 // softmax prob sums (aux loss)
__device__ int    g_cnt[KE];                // tokens per expert
__device__ int    g_off[KE];                // prefix offsets
__device__ int    g_cur[KE];                // scatter cursors
__device__ int    g_atok[KA];               // assignment -> token
__device__ int    g_aexp[KA];               // assignment -> expert
__device__ float  g_awt[KA];                // assignment -> combine weight
__device__ int    g_slot[KA];               // (token,k) -> assignment row

__device__ __forceinline__ float rsqrt_acc(float v){
  float r = rsqrtf(v);
  r = r*(1.5f - 0.5f*v*r*r);   // one Newton step
  return r;
}
__device__ __forceinline__ float gelu_f(float v){
  // jax.nn.gelu approximate=True (tanh form)
  float u = 0.7978845608028654f*(v + 0.044715f*v*v*v);
  u = fminf(fmaxf(u,-15.f),15.f);
  float ez = __expf(2.f*u);
  return 0.5f*v*(1.f + (ez-1.f)/(ez+1.f));
}

__global__ void k_init(){
  int t = threadIdx.x;
  if (t<32) g_wsum[t]=0.f;
  if (t<16){ g_ps[t]=0.f; g_cnt[t]=0; g_cur[t]=0; }
}

// -------- pass 1: sum |w| per expert-matrix segment --------
__global__ void k_wsum(const float* __restrict__ w1, const float* __restrict__ w2){
  int seg = blockIdx.y;  // 0..31: 0-15 -> w1 experts, 16-31 -> w2 experts
  const float* base = (seg<16) ? (w1 + (size_t)seg*KSEG) : (w2 + (size_t)(seg-16)*KSEG);
  const int per_block = KSEG/128;                  // 32768 elems
  const float4* p = (const float4*)(base + (size_t)blockIdx.x*per_block);
  float s=0.f;
  for (int i=threadIdx.x; i<per_block/4; i+=256){
    float4 v = p[i];
    s += fabsf(v.x)+fabsf(v.y)+fabsf(v.z)+fabsf(v.w);
  }
  __shared__ float sm[256];
  sm[threadIdx.x]=s; __syncthreads();
  for (int st=128; st>0; st>>=1){
    if (threadIdx.x<st) sm[threadIdx.x]+=sm[threadIdx.x+st];
    __syncthreads();
  }
  if (threadIdx.x==0) atomicAdd(&g_wsum[seg], sm[0]);
}

// -------- pass 2: ternary-quantize weights to int8 scratch --------
__global__ void k_wquant(const float* __restrict__ w1, const float* __restrict__ w2){
  const size_t half4 = (size_t)KE*KSEG/4;
  const size_t total4 = 2*half4;
  for (size_t i = (size_t)blockIdx.x*blockDim.x + threadIdx.x; i < total4;
       i += (size_t)gridDim.x*blockDim.x){
    size_t e0 = i*4;
    int seg = (int)(e0 / KSEG);
    float4 v; int8_t* dst;
    if (i < half4){ v = ((const float4*)w1)[i]; dst = g_w1q + e0; }
    else          { v = ((const float4*)w2)[i-half4]; dst = g_w2q + (e0 - (size_t)KE*KSEG); }
    float mean = g_wsum[seg] * (1.f/(float)KSEG);
    float sc = 1.f / fmaxf(mean, 1e-5f);
    char4 q;
    q.x = (signed char)(int)fminf(fmaxf(rintf(v.x*sc),-1.f),1.f);
    q.y = (signed char)(int)fminf(fmaxf(rintf(v.y*sc),-1.f),1.f);
    q.z = (signed char)(int)fminf(fmaxf(rintf(v.z*sc),-1.f),1.f);
    q.w = (signed char)(int)fminf(fmaxf(rintf(v.w*sc),-1.f),1.f);
    *(char4*)dst = q;
  }
}

// -------- router: logits, softmax, top-2, aux stats, inv-rms --------
__global__ void k_router(const float* __restrict__ x, const float* __restrict__ rw){
  int t = blockIdx.x;
  int tid = threadIdx.x;   // 128 threads
  float acc[17];
  #pragma unroll
  for (int i=0;i<17;i++) acc[i]=0.f;
  const float* xr = x + (size_t)t*KD;
  #pragma unroll
  for (int j=0;j<8;j++){
    int k = tid + j*128;
    float xv = xr[k];
    acc[16] += xv*xv;
    #pragma unroll
    for (int e=0;e<16;e++) acc[e] += xv * __ldg(&rw[e*KD + k]);
  }
  __shared__ float red[128][17];
  #pragma unroll
  for (int i=0;i<17;i++) red[tid][i]=acc[i];
  __syncthreads();
  __shared__ float fin[17];
  if (tid < 17){
    float s=0.f;
    for (int j=0;j<128;j++) s += red[j][tid];
    fin[tid]=s;
  }
  __syncthreads();
  if (tid==0){
    g_ir[t] = rsqrt_acc(fin[16]*(1.f/(float)KD) + 1e-6f);
    float m = fin[0];
    for (int e=1;e<16;e++) m = fmaxf(m, fin[e]);
    float p[16]; float Z=0.f;
    for (int e=0;e<16;e++){ p[e]=__expf(fin[e]-m); Z+=p[e]; }
    float invZ = 1.f/Z;
    for (int e=0;e<16;e++){ p[e]*=invZ; atomicAdd(&g_ps[e], p[e]); }
    int i0=0;
    for (int e=1;e<16;e++) if (p[e]>p[i0]) i0=e;            // ties -> lowest index
    int i1=(i0==0)?1:0;
    for (int e=0;e<16;e++){ if (e!=i0 && p[e]>p[i1]) i1=e; }
    float s2 = p[i0]+p[i1]+1e-8f;
    g_te[2*t]=i0; g_te[2*t+1]=i1;
    g_tw[2*t]=p[i0]/s2; g_tw[2*t+1]=p[i1]/s2;
    atomicAdd(&g_cnt[i0],1); atomicAdd(&g_cnt[i1],1);
  }
}

__global__ void k_offaux(float* out_aux){
  if (threadIdx.x==0 && blockIdx.x==0){
    int off=0;
    for (int e=0;e<16;e++){ g_off[e]=off; off+=g_cnt[e]; }
    float aux=0.f;
    for (int e=0;e<16;e++)
      aux += ((float)g_cnt[e]/(float)KA) * (g_ps[e]/(float)KT);
    *out_aux = 16.f*aux;
  }
}

__global__ void k_scatter(){
  int t = blockIdx.x*blockDim.x + threadIdx.x;
  if (t>=KT) return;
  #pragma unroll
  for (int s=0;s<2;s++){
    int e = g_te[2*t+s];
    int pos = g_off[e] + atomicAdd(&g_cur[e],1);
    g_atok[pos]=t; g_aexp[pos]=e; g_awt[pos]=g_tw[2*t+s]; g_slot[2*t+s]=pos;
  }
}

// -------- build int8 activations for gemm1 (rmsnorm(x,g1[e]) -> act_quant) --------
__global__ void k_qa(const float* __restrict__ x, const float* __restrict__ g1){
  int a = blockIdx.x; int tid=threadIdx.x;   // 256 threads, 4 elems each
  int t = g_atok[a], e = g_aexp[a];
  float ir = g_ir[t];
  float4 xv = *(const float4*)(x  + (size_t)t*KD + tid*4);
  float4 gv = *(const float4*)(g1 + (size_t)e*KD + tid*4);
  float4 y = make_float4(xv.x*gv.x*ir, xv.y*gv.y*ir, xv.z*gv.z*ir, xv.w*gv.w*ir);
  float mx = fmaxf(fmaxf(fabsf(y.x),fabsf(y.y)),fmaxf(fabsf(y.z),fabsf(y.w)));
  __shared__ float sm[256];
  sm[tid]=mx; __syncthreads();
  for (int st=128;st>0;st>>=1){
    if (tid<st) sm[tid]=fmaxf(sm[tid],sm[tid+st]);
    __syncthreads();
  }
  float mv = fmaxf(sm[0],1e-5f);
  float sc = 127.f/mv;
  if (tid==0) g_ra[a] = mv*(1.f/127.f);
  char4 q;
  q.x=(signed char)(int)fminf(fmaxf(rintf(y.x*sc),-128.f),127.f);
  q.y=(signed char)(int)fminf(fmaxf(rintf(y.y*sc),-128.f),127.f);
  q.z=(signed char)(int)fminf(fmaxf(rintf(y.z*sc),-128.f),127.f);
  q.w=(signed char)(int)fminf(fmaxf(rintf(y.w*sc),-128.f),127.f);
  *(char4*)(g_qa + (size_t)a*KD + tid*4) = q;
}

// -------- rmsnorm(h,g2[e]) + act_quant -> qh --------
__global__ void k_hq(const float* __restrict__ g2){
  int a = blockIdx.x; int tid=threadIdx.x;   // 256 threads, 16 elems each
  int e = g_aexp[a];
  const float* hr = g_h + (size_t)a*KF;
  float4 y[4]; float ss=0.f, mx=0.f;
  #pragma unroll
  for (int j=0;j<4;j++){
    int k = tid*4 + j*1024;
    float4 hv = *(const float4*)(hr + k);
    float4 gv = *(const float4*)(g2 + (size_t)e*KF + k);
    ss += hv.x*hv.x+hv.y*hv.y+hv.z*hv.z+hv.w*hv.w;
    y[j] = make_float4(hv.x*gv.x, hv.y*gv.y, hv.z*gv.z, hv.w*gv.w);
    mx = fmaxf(mx, fmaxf(fmaxf(fabsf(y[j].x),fabsf(y[j].y)),
                         fmaxf(fabsf(y[j].z),fabsf(y[j].w))));
  }
  __shared__ float sms[256], smm[256];
  sms[tid]=ss; smm[tid]=mx; __syncthreads();
  for (int st=128;st>0;st>>=1){
    if (tid<st){ sms[tid]+=sms[tid+st]; smm[tid]=fmaxf(smm[tid],smm[tid+st]); }
    __syncthreads();
  }
  float ir = rsqrt_acc(sms[0]*(1.f/(float)KF)+1e-6f);
  float my = fmaxf(smm[0]*ir, 1e-5f);
  float sc = 127.f/my;
  if (tid==0) g_rh[a] = my*(1.f/127.f);
  float f = ir*sc;
  #pragma unroll
  for (int j=0;j<4;j++){
    int k = tid*4 + j*1024;
    char4 q;
    q.x=(signed char)(int)fminf(fmaxf(rintf(y[j].x*f),-128.f),127.f);
    q.y=(signed char)(int)fminf(fmaxf(rintf(y[j].y*f),-128.f),127.f);
    q.z=(signed char)(int)fminf(fmaxf(rintf(y[j].z*f),-128.f),127.f);
    q.w=(signed char)(int)fminf(fmaxf(rintf(y[j].w*f),-128.f),127.f);
    *(char4*)(g_qh + (size_t)a*KF + k)=q;
  }
}

// -------- int8 IMMA GEMM: 128x128x64 tiles, 8 warps (4m x 2n), warp 32x64 --------
template<bool G1, int KDIM, int NDIM>
__global__ __launch_bounds__(256) void k_gemm(){
  int e = blockIdx.z;
  int cnt = g_cnt[e];
  int m0 = blockIdx.y*128;
  if (m0 >= cnt) return;
  int n0 = blockIdx.x*128;
  int off = g_off[e];
  const int8_t* A = G1 ? g_qa : g_qh;
  const int8_t* B = (G1 ? g_w1q : g_w2q) + (size_t)e*KSEG;
  __shared__ int8_t As[128*80];   // +16B pad per row: conflict-free quads, 16B aligned
  __shared__ int8_t Bs[128*80];
  int tid=threadIdx.x, wid=tid>>5, lane=tid&31;
  int wm = wid&3, wn = wid>>2;
  int gid = lane>>2, tig = lane&3;
  int c[2][8][4];
  #pragma unroll
  for (int i=0;i<2;i++)
    #pragma unroll
    for (int j=0;j<8;j++)
      #pragma unroll
      for (int k=0;k<4;k++) c[i][j][k]=0;

  for (int k0=0;k0<KDIM;k0+=64){
    #pragma unroll
    for (int j=0;j<2;j++){
      int idx = tid + j*256;
      int row = idx>>2, ch = idx&3;
      int m = m0+row;
      int4 v = make_int4(0,0,0,0);
      if (m < cnt) v = *(const int4*)(A + (size_t)(off+m)*KDIM + k0 + ch*16);
      *(int4*)&As[row*80 + ch*16] = v;
    }
    #pragma unroll
    for (int j=0;j<2;j++){
      int idx = tid + j*256;
      int row = idx>>2, ch = idx&3;
      *(int4*)&Bs[row*80 + ch*16] =
        *(const int4*)(B + (size_t)(n0+row)*KDIM + k0 + ch*16);
    }
    __syncthreads();
    #pragma unroll
    for (int ks=0;ks<2;ks++){
      int a[2][4];
      #pragma unroll
      for (int mf=0;mf<2;mf++){
        int r = wm*32+mf*16+gid;
        int base = r*80 + ks*32 + tig*4;
        a[mf][0] = *(const int*)&As[base];
        a[mf][1] = *(const int*)&As[base+8*80];
        a[mf][2] = *(const int*)&As[base+16];
        a[mf][3] = *(const int*)&As[base+8*80+16];
      }
      #pragma unroll
      for (int nf=0;nf<8;nf++){
        int ccol = wn*64+nf*8+gid;
        int bbase = ccol*80 + ks*32 + tig*4;
        int b0 = *(const int*)&Bs[bbase];
        int b1 = *(const int*)&Bs[bbase+16];
        #pragma unroll
        for (int mf=0;mf<2;mf++){
          asm volatile(
            "mma.sync.aligned.m16n8k32.row.col.s32.s8.s8.s32 "
            "{%0,%1,%2,%3},{%4,%5,%6,%7},{%8,%9},{%0,%1,%2,%3};\n"
            : "+r"(c[mf][nf][0]),"+r"(c[mf][nf][1]),
              "+r"(c[mf][nf][2]),"+r"(c[mf][nf][3])
            : "r"(a[mf][0]),"r"(a[mf][1]),"r"(a[mf][2]),"r"(a[mf][3]),
              "r"(b0),"r"(b1));
        }
      }
    }
    __syncthreads();
  }
  float wmean = fmaxf(g_wsum[G1 ? e : 16+e]*(1.f/(float)KSEG), 1e-5f);
  #pragma unroll
  for (int mf=0;mf<2;mf++){
    #pragma unroll
    for (int h2=0;h2<2;h2++){
      int m = m0 + wm*32 + mf*16 + gid + h2*8;
      if (m >= cnt) continue;
      int arow = off + m;
      float sc = (G1 ? g_ra[arow] : g_rh[arow]) * wmean;
      if (!G1) sc *= g_awt[arow];
      float* orow = (G1 ? g_h : g_part) + (size_t)arow*NDIM;
      #pragma unroll
      for (int nf=0;nf<8;nf++){
        int col = n0 + wn*64 + nf*8 + 2*tig;
        float v0 = (float)c[mf][nf][h2*2+0]*sc;
        float v1 = (float)c[mf][nf][h2*2+1]*sc;
        if (G1){ v0=gelu_f(v0); v1=gelu_f(v1); }
        *(float2*)(orow + col) = make_float2(v0,v1);
      }
    }
  }
}

// -------- combine the two expert contributions per token (deterministic) --------
__global__ void k_combine(float* __restrict__ out){
  int i = blockIdx.x*blockDim.x + threadIdx.x;   // 1,048,576 threads, one float4 each
  int t  = i >> 8;      // KD/4 = 256 float4 per token
  int d4 = i & 255;
  int p0 = g_slot[2*t], p1 = g_slot[2*t+1];
  float4 a = *(const float4*)(g_part + (size_t)p0*KD + d4*4);
  float4 b = *(const float4*)(g_part + (size_t)p1*KD + d4*4);
  *(float4*)(out + (size_t)i*4) = make_float4(a.x+b.x, a.y+b.y, a.z+b.z, a.w+b.w);
}

extern "C" void kernel_launch(void* const* d_in, const int* in_sizes, int n_in,
                              void* d_out, int out_size){
  (void)in_sizes; (void)n_in;
  const float* x  = (const float*)d_in[0];
  const float* rw = (const float*)d_in[1];
  const float* w1 = (const float*)d_in[2];
  const float* g1 = (const float*)d_in[3];
  const float* w2 = (const float*)d_in[4];
  const float* g2 = (const float*)d_in[5];
  float* out = (float*)d_out;

  k_init<<<1,64>>>();
  k_wsum<<<dim3(128,32),256>>>(w1,w2);
  k_wquant<<<16384,256>>>(w1,w2);
  k_router<<<KT,128>>>(x,rw);
  k_offaux<<<1,32>>>(out + (size_t)out_size - 1);   // aux loss -> last element
  k_scatter<<<16,256>>>();
  k_qa<<<KA,256>>>(x,g1);
  k_gemm<true,KD,KF><<<dim3(KF/128, 32, KE),256>>>();
  k_hq<<<KA,256>>>(g2);
  k_gemm<false,KF,KD><<<dim3(KD/128, 32, KE),256>>>();
  k_combine<<<4096,256>>>(out);
}

// round 7
// speedup vs baseline: 1.0580x; 1.0580x over previous
#include <cuda_runtime.h>
#include <cstdint>

#define KE 16
#define KD 1024
#define KF 4096
#define KT 4096
#define KA 8192
#define KSEG 4194304  /* KF*KD elements per expert matrix */

// ---------------- device scratch (static; no allocations) ----------------
__device__ int8_t g_w1q[(size_t)KE*KSEG];   // 64 MB ternary int8
__device__ int8_t g_w2q[(size_t)KE*KSEG];   // 64 MB
__device__ int8_t g_qa[(size_t)KA*KD];      // 8 MB quantized activations (gemm1 A)
__device__ int8_t g_qh[(size_t)KA*KF];      // 32 MB quantized hidden (gemm2 A)
__device__ float  g_h[(size_t)KA*KF];       // 128 MB fp32 hidden (gelu output)
__device__ float  g_wsum[32];               // sum |w| per (matrix, expert)
__device__ float  g_ra[KA];                 // act scale (max/127) gemm1 rows
__device__ float  g_rh[KA];                 // act scale gemm2 rows
__device__ float  g_ir[KT];                 // per-token inv rms of x
__device__ int    g_te[KT*2];               // top-2 expert ids per token
__device__ float  g_tw[KT*2];               // top-2 combine weights
__device__ float  g_ps[KE];                 // softmax prob sums (aux loss)
__device__ int    g_cnt[KE];                // tokens per expert
__device__ int    g_off[KE];                // prefix offsets
__device__ int    g_cur[KE];                // scatter cursors
__device__ int    g_atok[KA];               // assignment -> token
__device__ int    g_aexp[KA];               // assignment -> expert
__device__ float  g_awt[KA];                // assignment -> combine weight

__device__ __forceinline__ float rsqrt_acc(float v){
  float r = rsqrtf(v);
  r = r*(1.5f - 0.5f*v*r*r);   // one Newton step
  return r;
}
__device__ __forceinline__ float gelu_f(float v){
  float u = 0.7978845608028654f*(v + 0.044715f*v*v*v);
  u = fminf(fmaxf(u,-15.f),15.f);
  float ez = __expf(2.f*u);
  return 0.5f*v*(1.f + (ez-1.f)/(ez+1.f));
}

__global__ void k_init(){
  int t = threadIdx.x;
  if (t<32) g_wsum[t]=0.f;
  if (t<16){ g_ps[t]=0.f; g_cnt[t]=0; g_cur[t]=0; }
}

// -------- pass 1: sum |w| per expert-matrix segment --------
__global__ void k_wsum(const float* __restrict__ w1, const float* __restrict__ w2){
  int seg = blockIdx.y;
  const float* base = (seg<16) ? (w1 + (size_t)seg*KSEG) : (w2 + (size_t)(seg-16)*KSEG);
  const int per_block = KSEG/128;
  const float4* p = (const float4*)(base + (size_t)blockIdx.x*per_block);
  float s=0.f;
  for (int i=threadIdx.x; i<per_block/4; i+=256){
    float4 v = p[i];
    s += fabsf(v.x)+fabsf(v.y)+fabsf(v.z)+fabsf(v.w);
  }
  __shared__ float sm[256];
  sm[threadIdx.x]=s; __syncthreads();
  for (int st=128; st>0; st>>=1){
    if (threadIdx.x<st) sm[threadIdx.x]+=sm[threadIdx.x+st];
    __syncthreads();
  }
  if (threadIdx.x==0) atomicAdd(&g_wsum[seg], sm[0]);
}

// -------- pass 2: ternary-quantize weights to int8 scratch --------
__global__ void k_wquant(const float* __restrict__ w1, const float* __restrict__ w2){
  const size_t half4 = (size_t)KE*KSEG/4;
  const size_t total4 = 2*half4;
  for (size_t i = (size_t)blockIdx.x*blockDim.x + threadIdx.x; i < total4;
       i += (size_t)gridDim.x*blockDim.x){
    size_t e0 = i*4;
    int seg = (int)(e0 / KSEG);
    float4 v; int8_t* dst;
    if (i < half4){ v = ((const float4*)w1)[i]; dst = g_w1q + e0; }
    else          { v = ((const float4*)w2)[i-half4]; dst = g_w2q + (e0 - (size_t)KE*KSEG); }
    float mean = g_wsum[seg] * (1.f/(float)KSEG);
    float sc = 1.f / fmaxf(mean, 1e-5f);
    char4 q;
    q.x = (signed char)(int)fminf(fmaxf(rintf(v.x*sc),-1.f),1.f);
    q.y = (signed char)(int)fminf(fmaxf(rintf(v.y*sc),-1.f),1.f);
    q.z = (signed char)(int)fminf(fmaxf(rintf(v.z*sc),-1.f),1.f);
    q.w = (signed char)(int)fminf(fmaxf(rintf(v.w*sc),-1.f),1.f);
    *(char4*)dst = q;
  }
}

// -------- router: one warp per token, register accumulation + shuffle reduce --------
__global__ void k_router(const float* __restrict__ x, const float* __restrict__ rw){
  int gw  = (blockIdx.x*blockDim.x + threadIdx.x)>>5;   // token id (grid exact: 4096 warps)
  int lane = threadIdx.x&31;
  const float* xr = x + (size_t)gw*KD;
  float acc[16]; float ss=0.f;
  #pragma unroll
  for (int e=0;e<16;e++) acc[e]=0.f;
  #pragma unroll
  for (int j=0;j<8;j++){
    int k = j*128 + lane*4;
    float4 xv = *(const float4*)(xr + k);
    ss += xv.x*xv.x+xv.y*xv.y+xv.z*xv.z+xv.w*xv.w;
    #pragma unroll
    for (int e=0;e<16;e++){
      float4 wv = __ldg((const float4*)(rw + e*KD + k));
      acc[e] += xv.x*wv.x+xv.y*wv.y+xv.z*wv.z+xv.w*wv.w;
    }
  }
  #pragma unroll
  for (int o=16;o>0;o>>=1){
    ss += __shfl_xor_sync(~0u, ss, o);
    #pragma unroll
    for (int e=0;e<16;e++) acc[e] += __shfl_xor_sync(~0u, acc[e], o);
  }
  if (lane==0){
    int t = gw;
    g_ir[t] = rsqrt_acc(ss*(1.f/(float)KD) + 1e-6f);
    float m = acc[0];
    #pragma unroll
    for (int e=1;e<16;e++) m = fmaxf(m, acc[e]);
    float p[16]; float Z=0.f;
    #pragma unroll
    for (int e=0;e<16;e++){ p[e]=__expf(acc[e]-m); Z+=p[e]; }
    float invZ = 1.f/Z;
    #pragma unroll
    for (int e=0;e<16;e++){ p[e]*=invZ; atomicAdd(&g_ps[e], p[e]); }
    int i0=0;
    for (int e=1;e<16;e++) if (p[e]>p[i0]) i0=e;
    int i1=(i0==0)?1:0;
    for (int e=0;e<16;e++){ if (e!=i0 && p[e]>p[i1]) i1=e; }
    float s2 = p[i0]+p[i1]+1e-8f;
    g_te[2*t]=i0; g_te[2*t+1]=i1;
    g_tw[2*t]=p[i0]/s2; g_tw[2*t+1]=p[i1]/s2;
    atomicAdd(&g_cnt[i0],1); atomicAdd(&g_cnt[i1],1);
  }
}

__global__ void k_offaux(float* out_aux){
  if (threadIdx.x==0 && blockIdx.x==0){
    int off=0;
    for (int e=0;e<16;e++){ g_off[e]=off; off+=g_cnt[e]; }
    float aux=0.f;
    for (int e=0;e<16;e++)
      aux += ((float)g_cnt[e]/(float)KA) * (g_ps[e]/(float)KT);
    *out_aux = 16.f*aux;
  }
}

__global__ void k_scatter(){
  int t = blockIdx.x*blockDim.x + threadIdx.x;
  if (t>=KT) return;
  #pragma unroll
  for (int s=0;s<2;s++){
    int e = g_te[2*t+s];
    int pos = g_off[e] + atomicAdd(&g_cur[e],1);
    g_atok[pos]=t; g_aexp[pos]=e; g_awt[pos]=g_tw[2*t+s];
  }
}

// -------- build int8 activations for gemm1 --------
__global__ void k_qa(const float* __restrict__ x, const float* __restrict__ g1){
  int a = blockIdx.x; int tid=threadIdx.x;
  int t = g_atok[a], e = g_aexp[a];
  float ir = g_ir[t];
  float4 xv = *(const float4*)(x  + (size_t)t*KD + tid*4);
  float4 gv = *(const float4*)(g1 + (size_t)e*KD + tid*4);
  float4 y = make_float4(xv.x*gv.x*ir, xv.y*gv.y*ir, xv.z*gv.z*ir, xv.w*gv.w*ir);
  float mx = fmaxf(fmaxf(fabsf(y.x),fabsf(y.y)),fmaxf(fabsf(y.z),fabsf(y.w)));
  __shared__ float sm[256];
  sm[tid]=mx; __syncthreads();
  for (int st=128;st>0;st>>=1){
    if (tid<st) sm[tid]=fmaxf(sm[tid],sm[tid+st]);
    __syncthreads();
  }
  float mv = fmaxf(sm[0],1e-5f);
  float sc = 127.f/mv;
  if (tid==0) g_ra[a] = mv*(1.f/127.f);
  char4 q;
  q.x=(signed char)(int)fminf(fmaxf(rintf(y.x*sc),-128.f),127.f);
  q.y=(signed char)(int)fminf(fmaxf(rintf(y.y*sc),-128.f),127.f);
  q.z=(signed char)(int)fminf(fmaxf(rintf(y.z*sc),-128.f),127.f);
  q.w=(signed char)(int)fminf(fmaxf(rintf(y.w*sc),-128.f),127.f);
  *(char4*)(g_qa + (size_t)a*KD + tid*4) = q;
}

// -------- rmsnorm(h,g2[e]) + act_quant -> qh --------
__global__ void k_hq(const float* __restrict__ g2){
  int a = blockIdx.x; int tid=threadIdx.x;
  int e = g_aexp[a];
  const float* hr = g_h + (size_t)a*KF;
  float4 y[4]; float ss=0.f, mx=0.f;
  #pragma unroll
  for (int j=0;j<4;j++){
    int k = tid*4 + j*1024;
    float4 hv = *(const float4*)(hr + k);
    float4 gv = *(const float4*)(g2 + (size_t)e*KF + k);
    ss += hv.x*hv.x+hv.y*hv.y+hv.z*hv.z+hv.w*hv.w;
    y[j] = make_float4(hv.x*gv.x, hv.y*gv.y, hv.z*gv.z, hv.w*gv.w);
    mx = fmaxf(mx, fmaxf(fmaxf(fabsf(y[j].x),fabsf(y[j].y)),
                         fmaxf(fabsf(y[j].z),fabsf(y[j].w))));
  }
  __shared__ float sms[256], smm[256];
  sms[tid]=ss; smm[tid]=mx; __syncthreads();
  for (int st=128;st>0;st>>=1){
    if (tid<st){ sms[tid]+=sms[tid+st]; smm[tid]=fmaxf(smm[tid],smm[tid+st]); }
    __syncthreads();
  }
  float ir = rsqrt_acc(sms[0]*(1.f/(float)KF)+1e-6f);
  float my = fmaxf(smm[0]*ir, 1e-5f);
  float sc = 127.f/my;
  if (tid==0) g_rh[a] = my*(1.f/127.f);
  float f = ir*sc;
  #pragma unroll
  for (int j=0;j<4;j++){
    int k = tid*4 + j*1024;
    char4 q;
    q.x=(signed char)(int)fminf(fmaxf(rintf(y[j].x*f),-128.f),127.f);
    q.y=(signed char)(int)fminf(fmaxf(rintf(y[j].y*f),-128.f),127.f);
    q.z=(signed char)(int)fminf(fmaxf(rintf(y[j].z*f),-128.f),127.f);
    q.w=(signed char)(int)fminf(fmaxf(rintf(y[j].w*f),-128.f),127.f);
    *(char4*)(g_qh + (size_t)a*KF + k)=q;
  }
}

// ======== pipelined int8 IMMA GEMM ========
// 128x128x64 tiles, 3-stage cp.async pipeline, ldmatrix fragment loads.
// smem layout: 64B rows, 16B chunks XOR-swizzled: chunk' = chunk ^ ((row>>1)&3)
#define CP16(dst, src, sz) \
  asm volatile("cp.async.cg.shared.global [%0],[%1],16,%2;\n"::"r"(dst),"l"(src),"r"(sz))
#define CP_COMMIT() asm volatile("cp.async.commit_group;\n"::)
#define CP_WAIT2()  asm volatile("cp.async.wait_group 2;\n"::: "memory")
#define LDSM4(r0,r1,r2,r3,addr) \
  asm volatile("ldmatrix.sync.aligned.m8n8.x4.shared.b16 {%0,%1,%2,%3},[%4];\n" \
    : "=r"(r0),"=r"(r1),"=r"(r2),"=r"(r3) : "r"(addr))

template<bool G1, int KDIM, int NDIM>
__global__ __launch_bounds__(256,2) void k_gemm(float* __restrict__ out){
  int e = blockIdx.z;
  int cnt = g_cnt[e];
  int m0 = blockIdx.y*128;
  if (m0 >= cnt) return;
  int n0 = blockIdx.x*128;
  int off = g_off[e];
  const int8_t* A = G1 ? g_qa : g_qh;
  const int8_t* B = (G1 ? g_w1q : g_w2q) + (size_t)e*KSEG;

  __shared__ __align__(128) int8_t sA[3*8192];
  __shared__ __align__(128) int8_t sB[3*8192];
  uint32_t aSm = (uint32_t)__cvta_generic_to_shared(sA);
  uint32_t bSm = (uint32_t)__cvta_generic_to_shared(sB);

  int tid = threadIdx.x, wid = tid>>5, lane = tid&31;
  int wm = wid&3, wn = wid>>2;

  // ---- loader setup: each thread fills rows lr and lr+64, chunk lc ----
  int lr = tid>>2, lc = tid&3;
  int mr0 = m0+lr, mr1 = m0+lr+64;
  int szA0 = (mr0<cnt)?16:0, szA1 = (mr1<cnt)?16:0;
  int cr0 = min(mr0,cnt-1), cr1 = min(mr1,cnt-1);
  const int8_t* gA0 = A + (size_t)(off+cr0)*KDIM + lc*16;
  const int8_t* gA1 = A + (size_t)(off+cr1)*KDIM + lc*16;
  const int8_t* gB0 = B + (size_t)(n0+lr)*KDIM + lc*16;
  const int8_t* gB1 = gB0 + (size_t)64*KDIM;
  uint32_t sw = (uint32_t)((lc ^ ((lr>>1)&3))<<4);
  uint32_t dA0 = (uint32_t)lr*64 + sw, dA1 = dA0 + 64*64;
  uint32_t dB0 = dA0, dB1 = dA1;

  // ---- ldmatrix lane addressing ----
  int rAoff[2], sAx[2];
  #pragma unroll
  for (int mf=0;mf<2;mf++){
    int r = wm*32 + mf*16 + (lane&15);
    rAoff[mf] = r*64; sAx[mf] = (r>>1)&3;
  }
  int aHi = lane>>4;
  int rBoff[4], sBx[4];
  #pragma unroll
  for (int p=0;p<4;p++){
    int r = wn*64 + p*16 + (lane&7) + ((lane>>4)<<3);
    rBoff[p] = r*64; sBx[p] = (r>>1)&3;
  }
  int bHi = (lane>>3)&1;

  int c[2][8][4];
  #pragma unroll
  for (int i=0;i<2;i++)
    #pragma unroll
    for (int j=0;j<8;j++)
      #pragma unroll
      for (int k=0;k<4;k++) c[i][j][k]=0;

  const int NK = KDIM/64;
  // prologue: stages 0,1
  #pragma unroll
  for (int s=0;s<2;s++){
    int k0 = s*64;
    uint32_t ab = aSm + s*8192, bb = bSm + s*8192;
    CP16(ab+dA0, gA0+k0, szA0);
    CP16(ab+dA1, gA1+k0, szA1);
    CP16(bb+dB0, gB0+k0, 16);
    CP16(bb+dB1, gB1+k0, 16);
    CP_COMMIT();
  }

  for (int kt=0; kt<NK; kt++){
    if (kt+2 < NK){
      int s = (kt+2)%3, k0 = (kt+2)*64;
      uint32_t ab = aSm + s*8192, bb = bSm + s*8192;
      CP16(ab+dA0, gA0+k0, szA0);
      CP16(ab+dA1, gA1+k0, szA1);
      CP16(bb+dB0, gB0+k0, 16);
      CP16(bb+dB1, gB1+k0, 16);
    }
    CP_COMMIT();
    CP_WAIT2();
    __syncthreads();

    int s = kt%3;
    uint32_t ab = aSm + s*8192, bb = bSm + s*8192;
    #pragma unroll
    for (int ks=0;ks<2;ks++){
      int a[2][4];
      #pragma unroll
      for (int mf=0;mf<2;mf++){
        uint32_t addr = ab + rAoff[mf] + (uint32_t)(((2*ks + aHi) ^ sAx[mf])<<4);
        LDSM4(a[mf][0],a[mf][1],a[mf][2],a[mf][3], addr);
      }
      int b[4][4];
      #pragma unroll
      for (int p=0;p<4;p++){
        uint32_t addr = bb + rBoff[p] + (uint32_t)(((2*ks + bHi) ^ sBx[p])<<4);
        LDSM4(b[p][0],b[p][1],b[p][2],b[p][3], addr);
      }
      #pragma unroll
      for (int p=0;p<4;p++){
        #pragma unroll
        for (int half=0;half<2;half++){
          int nf = 2*p + half;
          int bb0 = b[p][half*2+0], bb1 = b[p][half*2+1];
          #pragma unroll
          for (int mf=0;mf<2;mf++){
            asm volatile(
              "mma.sync.aligned.m16n8k32.row.col.s32.s8.s8.s32 "
              "{%0,%1,%2,%3},{%4,%5,%6,%7},{%8,%9},{%0,%1,%2,%3};\n"
              : "+r"(c[mf][nf][0]),"+r"(c[mf][nf][1]),
                "+r"(c[mf][nf][2]),"+r"(c[mf][nf][3])
              : "r"(a[mf][0]),"r"(a[mf][1]),"r"(a[mf][2]),"r"(a[mf][3]),
                "r"(bb0),"r"(bb1));
          }
        }
      }
    }
    __syncthreads();
  }

  // ---- epilogue ----
  int gid = lane>>2, tig = lane&3;
  float wmean = fmaxf(g_wsum[G1 ? e : 16+e]*(1.f/(float)KSEG), 1e-5f);
  #pragma unroll
  for (int mf=0;mf<2;mf++){
    #pragma unroll
    for (int h2=0;h2<2;h2++){
      int m = m0 + wm*32 + mf*16 + gid + h2*8;
      if (m >= cnt) continue;
      int arow = off + m;
      float sc = (G1 ? g_ra[arow] : g_rh[arow]) * wmean;
      if (G1){
        float* orow = g_h + (size_t)arow*NDIM;
        #pragma unroll
        for (int nf=0;nf<8;nf++){
          int col = n0 + wn*64 + nf*8 + 2*tig;
          float v0 = gelu_f((float)c[mf][nf][h2*2+0]*sc);
          float v1 = gelu_f((float)c[mf][nf][h2*2+1]*sc);
          *(float2*)(orow + col) = make_float2(v0,v1);
        }
      } else {
        sc *= g_awt[arow];
        int tok = g_atok[arow];
        float* orow = out + (size_t)tok*NDIM;
        #pragma unroll
        for (int nf=0;nf<8;nf++){
          int col = n0 + wn*64 + nf*8 + 2*tig;
          atomicAdd(orow + col,     (float)c[mf][nf][h2*2+0]*sc);
          atomicAdd(orow + col + 1, (float)c[mf][nf][h2*2+1]*sc);
        }
      }
    }
  }
}

extern "C" void kernel_launch(void* const* d_in, const int* in_sizes, int n_in,
                              void* d_out, int out_size){
  (void)in_sizes; (void)n_in;
  const float* x  = (const float*)d_in[0];
  const float* rw = (const float*)d_in[1];
  const float* w1 = (const float*)d_in[2];
  const float* g1 = (const float*)d_in[3];
  const float* w2 = (const float*)d_in[4];
  const float* g2 = (const float*)d_in[5];
  float* out = (float*)d_out;

  k_init<<<1,64>>>();
  cudaMemsetAsync(out, 0, (size_t)out_size*sizeof(float));
  k_wsum<<<dim3(128,32),256>>>(w1,w2);
  k_wquant<<<16384,256>>>(w1,w2);
  k_router<<<512,256>>>(x,rw);
  k_offaux<<<1,32>>>(out + (size_t)out_size - 1);
  k_scatter<<<16,256>>>();
  k_qa<<<KA,256>>>(x,g1);
  k_gemm<true,KD,KF><<<dim3(KF/128, 32, KE),256>>>(nullptr);
  k_hq<<<KA,256>>>(g2);
  k_gemm<false,KF,KD><<<dim3(KD/128, 32, KE),256>>>(out);
}

// round 10
// speedup vs baseline: 1.6136x; 1.5251x over previous
#include <cuda_runtime.h>
#include <cuda_bf16.h>
#include <cstdint>

#define KE 16
#define KD 1024
#define KF 4096
#define KT 4096
#define KA 8192
#define KSEG 4194304  /* KF*KD elements per expert matrix */

typedef __nv_bfloat16 bf16;

// ---------------- device scratch (static; no allocations) ----------------
__device__ bf16   g_w1b[(size_t)KE*KSEG];   // 128 MB ternary (exact in bf16)
__device__ bf16   g_w2b[(size_t)KE*KSEG];   // 128 MB
__device__ bf16   g_qa[(size_t)KA*KD];      // 16 MB quantized activations (gemm1 A)
__device__ bf16   g_qh[(size_t)KA*KF];      // 64 MB quantized hidden (gemm2 A)
__device__ float  g_h[(size_t)KA*KF];       // 128 MB fp32 hidden (gelu output)
__device__ float  g_wsum[32];
__device__ float  g_ra[KA];
__device__ float  g_rh[KA];
__device__ float  g_ir[KT];
__device__ int    g_te[KT*2];
__device__ float  g_tw[KT*2];
__device__ float  g_ps[KE];
__device__ int    g_cnt[KE];
__device__ int    g_off[KE];
__device__ int    g_cur[KE];
__device__ int    g_atok[KA];
__device__ int    g_aexp[KA];
__device__ float  g_awt[KA];

__device__ __forceinline__ float rsqrt_acc(float v){
  float r = rsqrtf(v);
  r = r*(1.5f - 0.5f*v*r*r);
  return r;
}
__device__ __forceinline__ float gelu_f(float v){
  float u = 0.7978845608028654f*(v + 0.044715f*v*v*v);
  u = fminf(fmaxf(u,-15.f),15.f);
  float ez = __expf(2.f*u);
  return 0.5f*v*(1.f + (ez-1.f)/(ez+1.f));
}

// ---------------- small kernels ----------------
__global__ void k_init(){
  int t = threadIdx.x;
  if (t<32) g_wsum[t]=0.f;
  if (t<16){ g_ps[t]=0.f; g_cnt[t]=0; g_cur[t]=0; }
}

__global__ void k_wsum(const float* __restrict__ w1, const float* __restrict__ w2){
  int seg = blockIdx.y;
  const float* base = (seg<16) ? (w1 + (size_t)seg*KSEG) : (w2 + (size_t)(seg-16)*KSEG);
  const int per_block = KSEG/128;
  const float4* p = (const float4*)(base + (size_t)blockIdx.x*per_block);
  float s=0.f;
  for (int i=threadIdx.x; i<per_block/4; i+=256){
    float4 v = p[i];
    s += fabsf(v.x)+fabsf(v.y)+fabsf(v.z)+fabsf(v.w);
  }
  __shared__ float sm[256];
  sm[threadIdx.x]=s; __syncthreads();
  for (int st=128; st>0; st>>=1){
    if (threadIdx.x<st) sm[threadIdx.x]+=sm[threadIdx.x+st];
    __syncthreads();
  }
  if (threadIdx.x==0) atomicAdd(&g_wsum[seg], sm[0]);
}

__global__ void k_wquant(const float* __restrict__ w1, const float* __restrict__ w2){
  const size_t half4 = (size_t)KE*KSEG/4;
  const size_t total4 = 2*half4;
  for (size_t i = (size_t)blockIdx.x*blockDim.x + threadIdx.x; i < total4;
       i += (size_t)gridDim.x*blockDim.x){
    size_t e0 = i*4;
    int seg = (int)(e0 / KSEG);
    float4 v; bf16* dst;
    if (i < half4){ v = ((const float4*)w1)[i]; dst = g_w1b + e0; }
    else          { v = ((const float4*)w2)[i-half4]; dst = g_w2b + (e0 - (size_t)KE*KSEG); }
    float mean = g_wsum[seg] * (1.f/(float)KSEG);
    float sc = 1.f / fmaxf(mean, 1e-5f);
    bf16 b0 = __float2bfloat16(fminf(fmaxf(rintf(v.x*sc),-1.f),1.f));
    bf16 b1 = __float2bfloat16(fminf(fmaxf(rintf(v.y*sc),-1.f),1.f));
    bf16 b2 = __float2bfloat16(fminf(fmaxf(rintf(v.z*sc),-1.f),1.f));
    bf16 b3 = __float2bfloat16(fminf(fmaxf(rintf(v.w*sc),-1.f),1.f));
    ushort4 u;
    u.x = *(unsigned short*)&b0; u.y = *(unsigned short*)&b1;
    u.z = *(unsigned short*)&b2; u.w = *(unsigned short*)&b3;
    *(ushort4*)dst = u;
  }
}

__global__ __launch_bounds__(256) void k_router(const float* __restrict__ x,
                                                const float* __restrict__ rw){
  int gw  = (blockIdx.x*blockDim.x + threadIdx.x)>>5;
  int lane = threadIdx.x&31;
  const float* xr = x + (size_t)gw*KD;
  float acc[16]; float ss=0.f;
  #pragma unroll
  for (int e=0;e<16;e++) acc[e]=0.f;
  #pragma unroll 1
  for (int j=0;j<8;j++){
    int k = j*128 + lane*4;
    float4 xv = *(const float4*)(xr + k);
    ss += xv.x*xv.x+xv.y*xv.y+xv.z*xv.z+xv.w*xv.w;
    #pragma unroll
    for (int e=0;e<16;e++){
      float4 wv = __ldg((const float4*)(rw + e*KD + k));
      acc[e] += xv.x*wv.x+xv.y*wv.y+xv.z*wv.z+xv.w*wv.w;
    }
  }
  #pragma unroll
  for (int o=16;o>0;o>>=1){
    ss += __shfl_xor_sync(~0u, ss, o);
    #pragma unroll
    for (int e=0;e<16;e++) acc[e] += __shfl_xor_sync(~0u, acc[e], o);
  }
  if (lane==0){
    int t = gw;
    g_ir[t] = rsqrt_acc(ss*(1.f/(float)KD) + 1e-6f);
    float m = acc[0];
    #pragma unroll
    for (int e=1;e<16;e++) m = fmaxf(m, acc[e]);
    float p[16]; float Z=0.f;
    #pragma unroll
    for (int e=0;e<16;e++){ p[e]=__expf(acc[e]-m); Z+=p[e]; }
    float invZ = 1.f/Z;
    #pragma unroll
    for (int e=0;e<16;e++){ p[e]*=invZ; atomicAdd(&g_ps[e], p[e]); }
    int i0=0;
    for (int e=1;e<16;e++) if (p[e]>p[i0]) i0=e;
    int i1=(i0==0)?1:0;
    for (int e=0;e<16;e++){ if (e!=i0 && p[e]>p[i1]) i1=e; }
    float s2 = p[i0]+p[i1]+1e-8f;
    g_te[2*t]=i0; g_te[2*t+1]=i1;
    g_tw[2*t]=p[i0]/s2; g_tw[2*t+1]=p[i1]/s2;
    atomicAdd(&g_cnt[i0],1); atomicAdd(&g_cnt[i1],1);
  }
}

__global__ void k_offaux(float* out_aux){
  if (threadIdx.x==0 && blockIdx.x==0){
    int off=0;
    for (int e=0;e<16;e++){ g_off[e]=off; off+=g_cnt[e]; }
    float aux=0.f;
    for (int e=0;e<16;e++)
      aux += ((float)g_cnt[e]/(float)KA) * (g_ps[e]/(float)KT);
    *out_aux = 16.f*aux;
  }
}

__global__ void k_scatter(){
  int t = blockIdx.x*blockDim.x + threadIdx.x;
  if (t>=KT) return;
  #pragma unroll
  for (int s=0;s<2;s++){
    int e = g_te[2*t+s];
    int pos = g_off[e] + atomicAdd(&g_cur[e],1);
    g_atok[pos]=t; g_aexp[pos]=e; g_awt[pos]=g_tw[2*t+s];
  }
}

__global__ void k_qa(const float* __restrict__ x, const float* __restrict__ g1){
  int a = blockIdx.x; int tid=threadIdx.x;
  int t = g_atok[a], e = g_aexp[a];
  float ir = g_ir[t];
  float4 xv = *(const float4*)(x  + (size_t)t*KD + tid*4);
  float4 gv = *(const float4*)(g1 + (size_t)e*KD + tid*4);
  float4 y = make_float4(xv.x*gv.x*ir, xv.y*gv.y*ir, xv.z*gv.z*ir, xv.w*gv.w*ir);
  float mx = fmaxf(fmaxf(fabsf(y.x),fabsf(y.y)),fmaxf(fabsf(y.z),fabsf(y.w)));
  __shared__ float sm[256];
  sm[tid]=mx; __syncthreads();
  for (int st=128;st>0;st>>=1){
    if (tid<st) sm[tid]=fmaxf(sm[tid],sm[tid+st]);
    __syncthreads();
  }
  float mv = fmaxf(sm[0],1e-5f);
  float sc = 127.f/mv;
  if (tid==0) g_ra[a] = mv*(1.f/127.f);
  float q0=fminf(fmaxf(rintf(y.x*sc),-128.f),127.f);
  float q1=fminf(fmaxf(rintf(y.y*sc),-128.f),127.f);
  float q2=fminf(fmaxf(rintf(y.z*sc),-128.f),127.f);
  float q3=fminf(fmaxf(rintf(y.w*sc),-128.f),127.f);
  bf16 b0=__float2bfloat16(q0), b1=__float2bfloat16(q1);
  bf16 b2=__float2bfloat16(q2), b3=__float2bfloat16(q3);
  ushort4 u;
  u.x=*(unsigned short*)&b0; u.y=*(unsigned short*)&b1;
  u.z=*(unsigned short*)&b2; u.w=*(unsigned short*)&b3;
  *(ushort4*)(g_qa + (size_t)a*KD + tid*4) = u;
}

__global__ void k_hq(const float* __restrict__ g2){
  int a = blockIdx.x; int tid=threadIdx.x;
  int e = g_aexp[a];
  const float* hr = g_h + (size_t)a*KF;
  float4 y[4]; float ss=0.f, mx=0.f;
  #pragma unroll
  for (int j=0;j<4;j++){
    int k = tid*4 + j*1024;
    float4 hv = *(const float4*)(hr + k);
    float4 gv = *(const float4*)(g2 + (size_t)e*KF + k);
    ss += hv.x*hv.x+hv.y*hv.y+hv.z*hv.z+hv.w*hv.w;
    y[j] = make_float4(hv.x*gv.x, hv.y*gv.y, hv.z*gv.z, hv.w*gv.w);
    mx = fmaxf(mx, fmaxf(fmaxf(fabsf(y[j].x),fabsf(y[j].y)),
                         fmaxf(fabsf(y[j].z),fabsf(y[j].w))));
  }
  __shared__ float sms[256], smm[256];
  sms[tid]=ss; smm[tid]=mx; __syncthreads();
  for (int st=128;st>0;st>>=1){
    if (tid<st){ sms[tid]+=sms[tid+st]; smm[tid]=fmaxf(smm[tid],smm[tid+st]); }
    __syncthreads();
  }
  float ir = rsqrt_acc(sms[0]*(1.f/(float)KF)+1e-6f);
  float my = fmaxf(smm[0]*ir, 1e-5f);
  float sc = 127.f/my;
  if (tid==0) g_rh[a] = my*(1.f/127.f);
  float f = ir*sc;
  #pragma unroll
  for (int j=0;j<4;j++){
    int k = tid*4 + j*1024;
    float q0=fminf(fmaxf(rintf(y[j].x*f),-128.f),127.f);
    float q1=fminf(fmaxf(rintf(y[j].y*f),-128.f),127.f);
    float q2=fminf(fmaxf(rintf(y[j].z*f),-128.f),127.f);
    float q3=fminf(fmaxf(rintf(y[j].w*f),-128.f),127.f);
    bf16 b0=__float2bfloat16(q0), b1=__float2bfloat16(q1);
    bf16 b2=__float2bfloat16(q2), b3=__float2bfloat16(q3);
    ushort4 u;
    u.x=*(unsigned short*)&b0; u.y=*(unsigned short*)&b1;
    u.z=*(unsigned short*)&b2; u.w=*(unsigned short*)&b3;
    *(ushort4*)(g_qh + (size_t)a*KF + k)=u;
  }
}

// ======== pipelined bf16 HMMA GEMM ========
// 128x128x64 tiles, 3-stage cp.async, ldmatrix b16 fragments.
// smem per stage: A 128x128B (16KB) + B 128x128B (16KB). Rows = 128B (64 bf16),
// 16B chunks XOR-swizzled: chunk' = chunk ^ (row&7).
#define CP16(dst, src, sz) \
  asm volatile("cp.async.cg.shared.global [%0],[%1],16,%2;\n"::"r"(dst),"l"(src),"r"(sz))
#define CP_COMMIT() asm volatile("cp.async.commit_group;\n"::)
#define CP_WAIT2()  asm volatile("cp.async.wait_group 2;\n"::: "memory")
#define LDSM4(r0,r1,r2,r3,addr) \
  asm volatile("ldmatrix.sync.aligned.m8n8.x4.shared.b16 {%0,%1,%2,%3},[%4];\n" \
    : "=r"(r0),"=r"(r1),"=r"(r2),"=r"(r3) : "r"(addr))

#define DSMEM (3*32768)

template<bool G1, int KDIM, int NDIM>
__global__ __launch_bounds__(256,2) void k_gemm(float* __restrict__ out){
  extern __shared__ char dynsm[];
  int e = blockIdx.z;
  int cnt = g_cnt[e];
  int m0 = blockIdx.y*128;
  if (m0 >= cnt) return;
  int n0 = blockIdx.x*128;
  int off = g_off[e];
  const bf16* A = G1 ? g_qa : g_qh;
  const bf16* B = (G1 ? g_w1b : g_w2b) + (size_t)e*KSEG;

  uint32_t sbase = (uint32_t)__cvta_generic_to_shared(dynsm);

  int tid = threadIdx.x, wid = tid>>5, lane = tid&31;
  int wm = wid&3, wn = wid>>2;

  // ---- loader setup: thread -> row = tid>>1 (0..127), chunks (tid&1)*4..+3 ----
  int lr = tid>>1;
  int lcb = (tid&1)*4;
  int swr = lr&7;
  int mA = m0 + lr;
  int szA = (mA < cnt) ? 16 : 0;
  const bf16* gA = A + (size_t)(off + min(mA, cnt-1))*KDIM;
  const bf16* gB = B + (size_t)(n0 + lr)*KDIM;
  uint32_t rowoff = (uint32_t)lr*128;

  // ---- ldmatrix lane addressing ----
  uint32_t rAoff[2]; int rAsw[2];
  #pragma unroll
  for (int mf=0;mf<2;mf++){
    int r = wm*32 + mf*16 + (lane&15);
    rAoff[mf] = (uint32_t)r*128; rAsw[mf] = r&7;
  }
  int aHi = lane>>4;
  uint32_t rBoff[4]; int rBsw[4];
  #pragma unroll
  for (int p=0;p<4;p++){
    int r = wn*64 + p*16 + (lane&7) + ((lane>>4)<<3);
    rBoff[p] = (uint32_t)r*128; rBsw[p] = r&7;
  }
  int bHi = (lane>>3)&1;

  float c[2][8][4];
  #pragma unroll
  for (int i=0;i<2;i++)
    #pragma unroll
    for (int j=0;j<8;j++)
      #pragma unroll
      for (int k=0;k<4;k++) c[i][j][k]=0.f;

  const int NK = KDIM/64;
  // prologue: stages 0,1
  #pragma unroll
  for (int s=0;s<2;s++){
    size_t k0 = (size_t)s*64;
    uint32_t ab = sbase + s*32768;
    #pragma unroll
    for (int j=0;j<4;j++){
      int ch = lcb + j;
      uint32_t doff = rowoff + (uint32_t)((ch ^ swr)<<4);
      CP16(ab + doff,          gA + k0 + ch*8, szA);
      CP16(ab + 16384 + doff,  gB + k0 + ch*8, 16);
    }
    CP_COMMIT();
  }

  for (int kt=0; kt<NK; kt++){
    if (kt+2 < NK){
      int s = (kt+2)%3;
      size_t k0 = (size_t)(kt+2)*64;
      uint32_t ab = sbase + s*32768;
      #pragma unroll
      for (int j=0;j<4;j++){
        int ch = lcb + j;
        uint32_t doff = rowoff + (uint32_t)((ch ^ swr)<<4);
        CP16(ab + doff,          gA + k0 + ch*8, szA);
        CP16(ab + 16384 + doff,  gB + k0 + ch*8, 16);
      }
    }
    CP_COMMIT();
    CP_WAIT2();
    __syncthreads();

    uint32_t ab = sbase + (kt%3)*32768;
    uint32_t bb = ab + 16384;
    #pragma unroll
    for (int ks=0;ks<4;ks++){
      int a[2][4];
      #pragma unroll
      for (int mf=0;mf<2;mf++){
        uint32_t addr = ab + rAoff[mf] + (uint32_t)(((2*ks + aHi) ^ rAsw[mf])<<4);
        LDSM4(a[mf][0],a[mf][1],a[mf][2],a[mf][3], addr);
      }
      int b[4][4];
      #pragma unroll
      for (int p=0;p<4;p++){
        uint32_t addr = bb + rBoff[p] + (uint32_t)(((2*ks + bHi) ^ rBsw[p])<<4);
        LDSM4(b[p][0],b[p][1],b[p][2],b[p][3], addr);
      }
      #pragma unroll
      for (int p=0;p<4;p++){
        #pragma unroll
        for (int half=0;half<2;half++){
          int nf = 2*p + half;
          int bb0 = b[p][half*2+0], bb1 = b[p][half*2+1];
          #pragma unroll
          for (int mf=0;mf<2;mf++){
            asm volatile(
              "mma.sync.aligned.m16n8k16.row.col.f32.bf16.bf16.f32 "
              "{%0,%1,%2,%3},{%4,%5,%6,%7},{%8,%9},{%0,%1,%2,%3};\n"
              : "+f"(c[mf][nf][0]),"+f"(c[mf][nf][1]),
                "+f"(c[mf][nf][2]),"+f"(c[mf][nf][3])
              : "r"(a[mf][0]),"r"(a[mf][1]),"r"(a[mf][2]),"r"(a[mf][3]),
                "r"(bb0),"r"(bb1));
          }
        }
      }
    }
    __syncthreads();
  }

  // ---- epilogue ----
  int gid = lane>>2, tig = lane&3;
  float wmean = fmaxf(g_wsum[G1 ? e : 16+e]*(1.f/(float)KSEG), 1e-5f);
  #pragma unroll
  for (int mf=0;mf<2;mf++){
    #pragma unroll
    for (int h2=0;h2<2;h2++){
      int m = m0 + wm*32 + mf*16 + gid + h2*8;
      if (m >= cnt) continue;
      int arow = off + m;
      float sc = (G1 ? g_ra[arow] : g_rh[arow]) * wmean;
      if (G1){
        float* orow = g_h + (size_t)arow*NDIM;
        #pragma unroll
        for (int nf=0;nf<8;nf++){
          int col = n0 + wn*64 + nf*8 + 2*tig;
          float v0 = gelu_f(c[mf][nf][h2*2+0]*sc);
          float v1 = gelu_f(c[mf][nf][h2*2+1]*sc);
          *(float2*)(orow + col) = make_float2(v0,v1);
        }
      } else {
        sc *= g_awt[arow];
        int tok = g_atok[arow];
        float* orow = out + (size_t)tok*NDIM;
        #pragma unroll
        for (int nf=0;nf<8;nf++){
          int col = n0 + wn*64 + nf*8 + 2*tig;
          atomicAdd(orow + col,     c[mf][nf][h2*2+0]*sc);
          atomicAdd(orow + col + 1, c[mf][nf][h2*2+1]*sc);
        }
      }
    }
  }
}

extern "C" void kernel_launch(void* const* d_in, const int* in_sizes, int n_in,
                              void* d_out, int out_size){
  (void)in_sizes; (void)n_in;
  const float* x  = (const float*)d_in[0];
  const float* rw = (const float*)d_in[1];
  const float* w1 = (const float*)d_in[2];
  const float* g1 = (const float*)d_in[3];
  const float* w2 = (const float*)d_in[4];
  const float* g2 = (const float*)d_in[5];
  float* out = (float*)d_out;

  cudaFuncSetAttribute(k_gemm<true,KD,KF>,
                       cudaFuncAttributeMaxDynamicSharedMemorySize, DSMEM);
  cudaFuncSetAttribute(k_gemm<false,KF,KD>,
                       cudaFuncAttributeMaxDynamicSharedMemorySize, DSMEM);

  k_init<<<1,64>>>();
  cudaMemsetAsync(out, 0, (size_t)out_size*sizeof(float));
  k_wsum<<<dim3(128,32),256>>>(w1,w2);
  k_wquant<<<16384,256>>>(w1,w2);
  k_router<<<512,256>>>(x,rw);
  k_offaux<<<1,32>>>(out + (size_t)out_size - 1);
  k_scatter<<<16,256>>>();
  k_qa<<<KA,256>>>(x,g1);
  k_gemm<true,KD,KF><<<dim3(KF/128, 32, KE),256,DSMEM>>>(nullptr);
  k_hq<<<KA,256>>>(g2);
  k_gemm<false,KF,KD><<<dim3(KD/128, 32, KE),256,DSMEM>>>(out);
}